// round 7
// baseline (speedup 1.0000x reference)
#include <cuda_runtime.h>
#include <cuda_bf16.h>
#include <cstdint>

// Problem constants
constexpr int B_ = 4;
constexpr int T_ = 2048;
constexpr int E_ = 1024;
constexpr int H_ = 16;
constexpr int S_ = 64;

// ---------------------------------------------------------------------------
// Global scratch (bf16 hi/lo split). Static device arrays only.
// ---------------------------------------------------------------------------
__device__ __nv_bfloat16 g_Qh[(size_t)B_ * H_ * T_ * S_];   // (b,h,t,s), pre-scaled
__device__ __nv_bfloat16 g_Ql[(size_t)B_ * H_ * T_ * S_];
__device__ __nv_bfloat16 g_Kh[(size_t)B_ * H_ * T_ * S_];
__device__ __nv_bfloat16 g_Kl[(size_t)B_ * H_ * T_ * S_];
__device__ __nv_bfloat16 g_Vth[(size_t)B_ * H_ * S_ * T_];  // (b,h,s,t) TRANSPOSED
__device__ __nv_bfloat16 g_Vtl[(size_t)B_ * H_ * S_ * T_];
__device__ __nv_bfloat16 g_Ch[(size_t)B_ * T_ * E_];        // context (b,t,e)
__device__ __nv_bfloat16 g_Cl[(size_t)B_ * T_ * E_];
__device__ __nv_bfloat16 g_Wph[(size_t)E_ * E_];
__device__ __nv_bfloat16 g_Wpl[(size_t)E_ * E_];

// ---------------------------------------------------------------------------
// Baseline-PTX helpers (no sm_103a-only instructions!)
// ---------------------------------------------------------------------------
__device__ __forceinline__ uint32_t smem_u32(const void* p) {
    uint32_t a;
    asm("{ .reg .u64 t; cvta.to.shared.u64 t, %1; cvt.u32.u64 %0, t; }"
        : "=r"(a) : "l"(p));
    return a;
}

#define LDS32(r, a) asm volatile("ld.shared.b32 %0, [%1];" : "=r"(r) : "r"(a))

#define CP_ASYNC16(dst, src) \
    asm volatile("cp.async.cg.shared.global [%0], [%1], 16;" :: "r"(dst), "l"(src) : "memory")
#define CP_COMMIT() asm volatile("cp.async.commit_group;" ::: "memory")
#define CP_WAIT1()  asm volatile("cp.async.wait_group 1;" ::: "memory")
#define CP_WAIT0()  asm volatile("cp.async.wait_group 0;" ::: "memory")

// m16n8k16 row.col bf16 -> fp32 accumulate (baseline PTX, runs on HMMA)
__device__ __forceinline__ void mma16816(float d[4], const uint32_t a[4],
                                         uint32_t b0, uint32_t b1) {
    asm volatile(
        "mma.sync.aligned.m16n8k16.row.col.f32.bf16.bf16.f32 "
        "{%0,%1,%2,%3}, {%4,%5,%6,%7}, {%8,%9}, {%0,%1,%2,%3};"
        : "+f"(d[0]), "+f"(d[1]), "+f"(d[2]), "+f"(d[3])
        : "r"(a[0]), "r"(a[1]), "r"(a[2]), "r"(a[3]), "r"(b0), "r"(b1));
}

// hi/lo bf16 split
__device__ __forceinline__ void split2(float v, __nv_bfloat16& h, __nv_bfloat16& l) {
    h = __float2bfloat16(v);
    l = __float2bfloat16(v - __bfloat162float(h));
}
__device__ __forceinline__ uint32_t pack_bf2(__nv_bfloat16 a, __nv_bfloat16 b) {
    __nv_bfloat162 t;
    t.x = a; t.y = b;
    return *reinterpret_cast<uint32_t*>(&t);
}
__device__ __forceinline__ void split_pack(float v0, float v1, uint32_t& hw, uint32_t& lw) {
    __nv_bfloat16 h0, l0, h1, l1;
    split2(v0, h0, l0);
    split2(v1, h1, l1);
    hw = pack_bf2(h0, h1);
    lw = pack_bf2(l0, l1);
}

// ---------------------------------------------------------------------------
// Kernel 1: QKV projection (SIMT) -> bf16 hi/lo in MMA-ready layouts.
// Grid: (T/64, H, 3*B), 256 threads.
// ---------------------------------------------------------------------------
__global__ __launch_bounds__(256) void qkv_kernel(const float* __restrict__ x,
                                                  const float* __restrict__ Wq,
                                                  const float* __restrict__ Wk,
                                                  const float* __restrict__ Wv) {
    extern __shared__ float sm[];
    float(*sW)[65] = (float(*)[65])sm;
    float(*sX)[65] = (float(*)[65])(sm + 64 * 65);

    const int t0 = blockIdx.x * 64;
    const int h = blockIdx.y;
    const int b = blockIdx.z / 3;
    const int which = blockIdx.z % 3;  // 0=Q, 1=K, 2=V
    const int bh = b * H_ + h;
    const int tid = threadIdx.x;

    const float* W = (which == 0) ? Wq : (which == 1) ? Wk : Wv;

    for (int i = tid; i < S_ * S_; i += 256) {
        int r = i >> 6, c = i & 63;
        sW[r][c] = W[i];
    }
    const float* xp = x + ((size_t)b * T_ + t0) * E_ + h * S_;
    for (int i = tid; i < 64 * S_; i += 256) {
        int r = i >> 6, c = i & 63;
        sX[r][c] = xp[(size_t)r * E_ + c];
    }
    __syncthreads();

    const int tx = tid & 15, ty = tid >> 4;
    float acc[4][4] = {};

#pragma unroll 8
    for (int i = 0; i < S_; ++i) {
        float xv[4], wv[4];
#pragma unroll
        for (int ii = 0; ii < 4; ++ii) xv[ii] = sX[ty * 4 + ii][i];
#pragma unroll
        for (int jj = 0; jj < 4; ++jj) wv[jj] = sW[tx * 4 + jj][i];
#pragma unroll
        for (int ii = 0; ii < 4; ++ii)
#pragma unroll
            for (int jj = 0; jj < 4; ++jj) acc[ii][jj] += xv[ii] * wv[jj];
    }

    const float scale = (which < 2) ? 0.17677669529663688f : 1.0f;  // 1/1024^0.25

    if (which < 2) {
        uint32_t* gh = (uint32_t*)(which == 0 ? g_Qh : g_Kh);
        uint32_t* gl = (uint32_t*)(which == 0 ? g_Ql : g_Kl);
#pragma unroll
        for (int ii = 0; ii < 4; ++ii) {
            int t = t0 + ty * 4 + ii;
#pragma unroll
            for (int jj = 0; jj < 4; jj += 2) {
                int o = tx * 4 + jj;
                uint32_t hw, lw;
                split_pack(acc[ii][jj] * scale, acc[ii][jj + 1] * scale, hw, lw);
                size_t w = ((size_t)bh * T_ + t) * 32 + (o >> 1);
                gh[w] = hw;
                gl[w] = lw;
            }
        }
    } else {
        uint32_t* gh = (uint32_t*)g_Vth;
        uint32_t* gl = (uint32_t*)g_Vtl;
#pragma unroll
        for (int jj = 0; jj < 4; ++jj) {
            int s = tx * 4 + jj;
#pragma unroll
            for (int ii = 0; ii < 4; ii += 2) {
                int t = t0 + ty * 4 + ii;
                uint32_t hw, lw;
                split_pack(acc[ii][jj], acc[ii + 1][jj], hw, lw);
                size_t w = ((size_t)bh * 64 + s) * (T_ / 2) + (t >> 1);
                gh[w] = hw;
                gl[w] = lw;
            }
        }
    }
}

// ---------------------------------------------------------------------------
// Kernel 2: Wp -> bf16 hi/lo
// ---------------------------------------------------------------------------
__global__ __launch_bounds__(256) void wp_convert_kernel(const float* __restrict__ Wp) {
    int i = blockIdx.x * 256 + threadIdx.x;
    int stride = gridDim.x * 256;
    for (; i < E_ * E_; i += stride) {
        __nv_bfloat16 h, l;
        split2(Wp[i], h, l);
        g_Wph[i] = h;
        g_Wpl[i] = l;
    }
}

// ---------------------------------------------------------------------------
// Kernel 3: HMMA flash attention, occupancy-2 version.
// CTA = (b, h, 128 q-rows); 8 warps x 16 rows. KV tile = 64 keys (32 iters),
// double-buffered cp.async. Per 16-col "pair": S (2 n-tiles, 8 regs) -> exp
// -> P frag -> 24 PV MMAs. sacc and P frags never coexist -> <=128 regs.
// Dyn smem: 2 x 36864 = 73728 B -> 2 CTAs/SM.
// ---------------------------------------------------------------------------
constexpr int AT_KH = 0;          // 64 rows x 144 B (64 bf16 + 8 pad)
constexpr int AT_KL = 9216;
constexpr int AT_VH = 18432;      // 64 s-rows x 144 B (64 t-cols + pad)
constexpr int AT_VL = 27648;
constexpr int AT_BUF = 36864;
constexpr int ATTN_SMEM = 2 * AT_BUF;   // 73728

__device__ __forceinline__ void attn_load_tile(uint32_t sb, int buf, int bh, int kt,
                                               int tid) {
    uint32_t bb = sb + (buf ? AT_BUF : 0);
    const char* kh = (const char*)g_Kh;
    const char* kl = (const char*)g_Kl;
    const char* vh = (const char*)g_Vth;
    const char* vl = (const char*)g_Vtl;
#pragma unroll
    for (int i = tid; i < 512; i += 256) {   // K tile: 64 rows x 8 chunks of 16B
        int row = i >> 3, c = i & 7;
        long gb = ((long)(bh * T_ + kt + row)) * 128 + c * 16;
        uint32_t so = (uint32_t)(row * 144 + c * 16);
        CP_ASYNC16(bb + AT_KH + so, kh + gb);
        CP_ASYNC16(bb + AT_KL + so, kl + gb);
    }
#pragma unroll
    for (int i = tid; i < 512; i += 256) {   // Vt tile: 64 s-rows x 8 chunks
        int row = i >> 3, c = i & 7;
        long gb = ((long)(bh * 64 + row)) * (T_ * 2) + (long)kt * 2 + c * 16;
        uint32_t so = (uint32_t)(row * 144 + c * 16);
        CP_ASYNC16(bb + AT_VH + so, vh + gb);
        CP_ASYNC16(bb + AT_VL + so, vl + gb);
    }
}

__global__ __launch_bounds__(256, 2) void attn_kernel() {
    extern __shared__ char smc[];
    const uint32_t sb = smem_u32(smc);

    const int tid = threadIdx.x;
    const int w = tid >> 5;
    const int lane = tid & 31;
    const int g = lane >> 2;   // row within 8
    const int tg = lane & 3;   // col-pair index

    const int q0 = blockIdx.x * 128;
    const int bh = blockIdx.z * H_ + blockIdx.y;
    const int r0 = q0 + w * 16 + g;

    // ---- Q fragments from gmem (held for the whole kernel) ----
    uint32_t qh[4][4], ql[4][4];
    {
        const uint32_t* gqh = (const uint32_t*)g_Qh;
        const uint32_t* gql = (const uint32_t*)g_Ql;
        int base0 = (bh * T_ + r0) * 32;
        int base1 = (bh * T_ + r0 + 8) * 32;
#pragma unroll
        for (int kk = 0; kk < 4; ++kk) {
            int wd = kk * 8 + tg;
            qh[kk][0] = gqh[base0 + wd];
            qh[kk][1] = gqh[base1 + wd];
            qh[kk][2] = gqh[base0 + wd + 4];
            qh[kk][3] = gqh[base1 + wd + 4];
            ql[kk][0] = gql[base0 + wd];
            ql[kk][1] = gql[base1 + wd];
            ql[kk][2] = gql[base0 + wd + 4];
            ql[kk][3] = gql[base1 + wd + 4];
        }
    }

    float oacc[8][4] = {};
    float l0 = 0.f, l1 = 0.f;

    attn_load_tile(sb, 0, bh, 0, tid);
    CP_COMMIT();

    for (int it = 0; it < 32; ++it) {
        const int buf = it & 1;
        if (it < 31) {
            attn_load_tile(sb, buf ^ 1, bh, (it + 1) * 64, tid);
            CP_COMMIT();
            CP_WAIT1();
        } else {
            CP_WAIT0();
        }
        __syncthreads();

        const uint32_t kb = sb + (buf ? AT_BUF : 0);

#pragma unroll
        for (int pair = 0; pair < 4; ++pair) {
            // ---- S for n-tiles 2p, 2p+1 (16 key cols) ----
            float sa0[4] = {}, sa1[4] = {};
#pragma unroll
            for (int kk = 0; kk < 4; ++kk) {
                uint32_t ro = (uint32_t)((pair * 16 + g) * 144 + (kk * 8 + tg) * 4);
                uint32_t bh0, bh1, bl0, bl1;
                LDS32(bh0, kb + AT_KH + ro);
                LDS32(bh1, kb + AT_KH + ro + 16);
                LDS32(bl0, kb + AT_KL + ro);
                LDS32(bl1, kb + AT_KL + ro + 16);
                mma16816(sa0, qh[kk], bh0, bh1);
                mma16816(sa0, qh[kk], bl0, bl1);
                mma16816(sa0, ql[kk], bh0, bh1);
                uint32_t ro2 = ro + 8 * 144;
                LDS32(bh0, kb + AT_KH + ro2);
                LDS32(bh1, kb + AT_KH + ro2 + 16);
                LDS32(bl0, kb + AT_KL + ro2);
                LDS32(bl1, kb + AT_KL + ro2 + 16);
                mma16816(sa1, qh[kk], bh0, bh1);
                mma16816(sa1, qh[kk], bl0, bl1);
                mma16816(sa1, ql[kk], bh0, bh1);
            }

            // ---- exp + P fragment (max-free softmax) ----
            uint32_t pah[4], pal[4];
            {
                float e0 = __expf(sa0[0]);
                float e1 = __expf(sa0[1]);
                float e2 = __expf(sa0[2]);
                float e3 = __expf(sa0[3]);
                float e4 = __expf(sa1[0]);
                float e5 = __expf(sa1[1]);
                float e6 = __expf(sa1[2]);
                float e7 = __expf(sa1[3]);
                l0 += (e0 + e1) + (e4 + e5);
                l1 += (e2 + e3) + (e6 + e7);
                split_pack(e0, e1, pah[0], pal[0]);
                split_pack(e2, e3, pah[1], pal[1]);
                split_pack(e4, e5, pah[2], pal[2]);
                split_pack(e6, e7, pah[3], pal[3]);
            }

            // ---- O += P_pair @ V^T (k-cols 16p..16p+15) ----
#pragma unroll
            for (int nt = 0; nt < 8; ++nt) {
                uint32_t vo = (uint32_t)((nt * 8 + g) * 144 + (pair * 8 + tg) * 4);
                uint32_t bh0, bh1, bl0, bl1;
                LDS32(bh0, kb + AT_VH + vo);
                LDS32(bh1, kb + AT_VH + vo + 16);
                LDS32(bl0, kb + AT_VL + vo);
                LDS32(bl1, kb + AT_VL + vo + 16);
                mma16816(oacc[nt], pah, bh0, bh1);
                mma16816(oacc[nt], pah, bl0, bl1);
                mma16816(oacc[nt], pal, bh0, bh1);
            }
        }
        __syncthreads();
    }

    // ---- epilogue: reduce row sums over quad, normalize, write context ----
    l0 += __shfl_xor_sync(0xffffffffu, l0, 1);
    l0 += __shfl_xor_sync(0xffffffffu, l0, 2);
    l1 += __shfl_xor_sync(0xffffffffu, l1, 1);
    l1 += __shfl_xor_sync(0xffffffffu, l1, 2);
    const float inv0 = 1.0f / l0;
    const float inv1 = 1.0f / l1;

    uint32_t* ch = (uint32_t*)g_Ch;
    uint32_t* cl = (uint32_t*)g_Cl;
    const long wb0 = (long)(blockIdx.z * T_ + r0) * 512 + blockIdx.y * 32;
    const long wb1 = (long)(blockIdx.z * T_ + r0 + 8) * 512 + blockIdx.y * 32;
#pragma unroll
    for (int nt = 0; nt < 8; ++nt) {
        uint32_t hw, lw;
        split_pack(oacc[nt][0] * inv0, oacc[nt][1] * inv0, hw, lw);
        ch[wb0 + nt * 4 + tg] = hw;
        cl[wb0 + nt * 4 + tg] = lw;
        split_pack(oacc[nt][2] * inv1, oacc[nt][3] * inv1, hw, lw);
        ch[wb1 + nt * 4 + tg] = hw;
        cl[wb1 + nt * 4 + tg] = lw;
    }
}

// ---------------------------------------------------------------------------
// Kernel 4: HMMA output projection, occupancy-2 version. Y = C @ Wp^T + bp.
// CTA tile 128x128, K-chunks of 32, double-buffered cp.async.
// Dyn smem: 2 x 40960 = 81920 B -> 2 CTAs/SM. Grid (64, 8), 256 threads.
// ---------------------------------------------------------------------------
constexpr int PJ_AH = 0;           // 128 rows x 80 B (32 bf16 + 8 pad)
constexpr int PJ_AL = 10240;
constexpr int PJ_BH = 20480;
constexpr int PJ_BL = 30720;
constexpr int PJ_BUF = 40960;
constexpr int PROJ_SMEM = 2 * PJ_BUF;  // 81920

__device__ __forceinline__ void proj_load_tile(uint32_t sb, int buf, int m0, int n0,
                                               int kc, int tid) {
    uint32_t bb = sb + (buf ? PJ_BUF : 0);
    const char* ah = (const char*)g_Ch;
    const char* al = (const char*)g_Cl;
    const char* bh = (const char*)g_Wph;
    const char* bl = (const char*)g_Wpl;
#pragma unroll
    for (int i = tid; i < 512; i += 256) {  // 128 rows x 4 chunks of 16B
        int row = i >> 2, c = i & 3;
        uint32_t so = (uint32_t)(row * 80 + c * 16);
        long ga = ((long)(m0 + row) * E_ + kc * 32) * 2 + c * 16;
        long gb = ((long)(n0 + row) * E_ + kc * 32) * 2 + c * 16;
        CP_ASYNC16(bb + PJ_AH + so, ah + ga);
        CP_ASYNC16(bb + PJ_AL + so, al + ga);
        CP_ASYNC16(bb + PJ_BH + so, bh + gb);
        CP_ASYNC16(bb + PJ_BL + so, bl + gb);
    }
}

__global__ __launch_bounds__(256, 2) void proj_kernel(const float* __restrict__ bp,
                                                      float* __restrict__ out) {
    extern __shared__ char smc[];
    const uint32_t sb = smem_u32(smc);

    const int tid = threadIdx.x;
    const int w = tid >> 5;
    const int lane = tid & 31;
    const int g = lane >> 2;
    const int tg = lane & 3;

    const int m0 = blockIdx.x * 128;
    const int n0 = blockIdx.y * 128;

    float acc[16][4] = {};

    proj_load_tile(sb, 0, m0, n0, 0, tid);
    CP_COMMIT();

    for (int kc = 0; kc < 32; ++kc) {
        const int buf = kc & 1;
        if (kc < 31) {
            proj_load_tile(sb, buf ^ 1, m0, n0, kc + 1, tid);
            CP_COMMIT();
            CP_WAIT1();
        } else {
            CP_WAIT0();
        }
        __syncthreads();

        const uint32_t bb = sb + (buf ? PJ_BUF : 0);
        const uint32_t arow0 = (uint32_t)((w * 16 + g) * 80);
        const uint32_t arow1 = arow0 + 8 * 80;

#pragma unroll
        for (int kk = 0; kk < 2; ++kk) {
            uint32_t fah[4], fal[4];
            uint32_t wo = (uint32_t)((kk * 8 + tg) * 4);
            LDS32(fah[0], bb + PJ_AH + arow0 + wo);
            LDS32(fah[1], bb + PJ_AH + arow1 + wo);
            LDS32(fah[2], bb + PJ_AH + arow0 + wo + 16);
            LDS32(fah[3], bb + PJ_AH + arow1 + wo + 16);
            LDS32(fal[0], bb + PJ_AL + arow0 + wo);
            LDS32(fal[1], bb + PJ_AL + arow1 + wo);
            LDS32(fal[2], bb + PJ_AL + arow0 + wo + 16);
            LDS32(fal[3], bb + PJ_AL + arow1 + wo + 16);
#pragma unroll
            for (int nt = 0; nt < 16; ++nt) {
                uint32_t boff = (uint32_t)((nt * 8 + g) * 80) + wo;
                uint32_t bh0, bh1, bl0, bl1;
                LDS32(bh0, bb + PJ_BH + boff);
                LDS32(bh1, bb + PJ_BH + boff + 16);
                LDS32(bl0, bb + PJ_BL + boff);
                LDS32(bl1, bb + PJ_BL + boff + 16);
                mma16816(acc[nt], fah, bh0, bh1);
                mma16816(acc[nt], fah, bl0, bl1);
                mma16816(acc[nt], fal, bh0, bh1);
            }
        }
        __syncthreads();
    }

    // epilogue: add bias, write fp32
    const int mr0 = m0 + w * 16 + g;
    const int mr1 = mr0 + 8;
#pragma unroll
    for (int nt = 0; nt < 16; ++nt) {
        int col = n0 + nt * 8 + tg * 2;
        float b0 = __ldg(bp + col);
        float b1 = __ldg(bp + col + 1);
        float2 v0 = make_float2(acc[nt][0] + b0, acc[nt][1] + b1);
        float2 v1 = make_float2(acc[nt][2] + b0, acc[nt][3] + b1);
        *(float2*)(out + (long)mr0 * E_ + col) = v0;
        *(float2*)(out + (long)mr1 * E_ + col) = v1;
    }
}

// ---------------------------------------------------------------------------
// kernel_launch: inputs x, Wk, Wq, Wv, Wp, bp
// ---------------------------------------------------------------------------
extern "C" void kernel_launch(void* const* d_in, const int* in_sizes, int n_in,
                              void* d_out, int out_size) {
    (void)in_sizes; (void)n_in; (void)out_size;
    const float* x = (const float*)d_in[0];
    const float* Wk = (const float*)d_in[1];
    const float* Wq = (const float*)d_in[2];
    const float* Wv = (const float*)d_in[3];
    const float* Wp = (const float*)d_in[4];
    const float* bp = (const float*)d_in[5];
    float* out = (float*)d_out;

    constexpr int SMEM_QKV = 128 * 65 * 4;  // 33280

    cudaFuncSetAttribute(qkv_kernel, cudaFuncAttributeMaxDynamicSharedMemorySize, SMEM_QKV);
    cudaFuncSetAttribute(attn_kernel, cudaFuncAttributeMaxDynamicSharedMemorySize, ATTN_SMEM);
    cudaFuncSetAttribute(proj_kernel, cudaFuncAttributeMaxDynamicSharedMemorySize, PROJ_SMEM);

    qkv_kernel<<<dim3(T_ / 64, H_, 3 * B_), 256, SMEM_QKV>>>(x, Wq, Wk, Wv);
    wp_convert_kernel<<<256, 256>>>(Wp);
    attn_kernel<<<dim3(T_ / 128, H_, B_), 256, ATTN_SMEM>>>();
    proj_kernel<<<dim3((B_ * T_) / 128, E_ / 128), 256, PROJ_SMEM>>>(bp, out);
}

// round 10
// speedup vs baseline: 2.1406x; 2.1406x over previous
#include <cuda_runtime.h>
#include <cuda_fp16.h>
#include <cstdint>

// Problem constants
constexpr int B_ = 4;
constexpr int T_ = 2048;
constexpr int E_ = 1024;
constexpr int H_ = 16;
constexpr int S_ = 64;

// ---------------------------------------------------------------------------
// Global scratch (fp16). Static device arrays only.
// ---------------------------------------------------------------------------
__device__ __half g_Q[(size_t)B_ * H_ * T_ * S_];    // (b,h,t,s), pre-scaled
__device__ __half g_K[(size_t)B_ * H_ * T_ * S_];    // (b,h,t,s), pre-scaled
__device__ __half g_Vt[(size_t)B_ * H_ * S_ * T_];   // (b,h,s,t) TRANSPOSED
__device__ __half g_C[(size_t)B_ * T_ * E_];         // context (b,t,e)
__device__ __half g_Wp[(size_t)E_ * E_];

// ---------------------------------------------------------------------------
// Baseline-PTX helpers (portable to plain sm_103 target)
// ---------------------------------------------------------------------------
__device__ __forceinline__ uint32_t smem_u32(const void* p) {
    uint32_t a;
    asm("{ .reg .u64 t; cvta.to.shared.u64 t, %1; cvt.u32.u64 %0, t; }"
        : "=r"(a) : "l"(p));
    return a;
}

#define LDSM4(r0, r1, r2, r3, addr) \
    asm volatile("ldmatrix.sync.aligned.m8n8.x4.shared.b16 {%0,%1,%2,%3}, [%4];" \
                 : "=r"(r0), "=r"(r1), "=r"(r2), "=r"(r3) : "r"(addr))

#define CP_ASYNC16(dst, src) \
    asm volatile("cp.async.cg.shared.global [%0], [%1], 16;" :: "r"(dst), "l"(src) : "memory")
#define CP_COMMIT() asm volatile("cp.async.commit_group;" ::: "memory")
#define CP_WAIT1()  asm volatile("cp.async.wait_group 1;" ::: "memory")
#define CP_WAIT0()  asm volatile("cp.async.wait_group 0;" ::: "memory")

// m16n8k16 row.col fp16 -> fp32 accumulate (HMMA)
__device__ __forceinline__ void mma16816(float d[4], const uint32_t a[4],
                                         uint32_t b0, uint32_t b1) {
    asm volatile(
        "mma.sync.aligned.m16n8k16.row.col.f32.f16.f16.f32 "
        "{%0,%1,%2,%3}, {%4,%5,%6,%7}, {%8,%9}, {%0,%1,%2,%3};"
        : "+f"(d[0]), "+f"(d[1]), "+f"(d[2]), "+f"(d[3])
        : "r"(a[0]), "r"(a[1]), "r"(a[2]), "r"(a[3]), "r"(b0), "r"(b1));
}

__device__ __forceinline__ uint32_t h2(float a, float b) {
    __half2 v = __float22half2_rn(make_float2(a, b));
    return *reinterpret_cast<uint32_t*>(&v);
}

// ---------------------------------------------------------------------------
// Kernel 1: QKV projection (SIMT fp32 compute) -> fp16 outputs.
// Grid: (T/64, H, 3*B), 256 threads.
// ---------------------------------------------------------------------------
__global__ __launch_bounds__(256) void qkv_kernel(const float* __restrict__ x,
                                                  const float* __restrict__ Wq,
                                                  const float* __restrict__ Wk,
                                                  const float* __restrict__ Wv) {
    extern __shared__ float sm[];
    float(*sW)[65] = (float(*)[65])sm;
    float(*sX)[65] = (float(*)[65])(sm + 64 * 65);

    const int t0 = blockIdx.x * 64;
    const int h = blockIdx.y;
    const int b = blockIdx.z / 3;
    const int which = blockIdx.z % 3;  // 0=Q, 1=K, 2=V
    const int bh = b * H_ + h;
    const int tid = threadIdx.x;

    const float* W = (which == 0) ? Wq : (which == 1) ? Wk : Wv;

    for (int i = tid; i < S_ * S_; i += 256) {
        int r = i >> 6, c = i & 63;
        sW[r][c] = W[i];
    }
    const float* xp = x + ((size_t)b * T_ + t0) * E_ + h * S_;
    for (int i = tid; i < 64 * S_; i += 256) {
        int r = i >> 6, c = i & 63;
        sX[r][c] = xp[(size_t)r * E_ + c];
    }
    __syncthreads();

    const int tx = tid & 15, ty = tid >> 4;
    float acc[4][4] = {};

#pragma unroll 8
    for (int i = 0; i < S_; ++i) {
        float xv[4], wv[4];
#pragma unroll
        for (int ii = 0; ii < 4; ++ii) xv[ii] = sX[ty * 4 + ii][i];
#pragma unroll
        for (int jj = 0; jj < 4; ++jj) wv[jj] = sW[tx * 4 + jj][i];
#pragma unroll
        for (int ii = 0; ii < 4; ++ii)
#pragma unroll
            for (int jj = 0; jj < 4; ++jj) acc[ii][jj] += xv[ii] * wv[jj];
    }

    const float scale = (which < 2) ? 0.17677669529663688f : 1.0f;  // 1/1024^0.25

    if (which < 2) {
        uint32_t* gq = (uint32_t*)(which == 0 ? g_Q : g_K);
#pragma unroll
        for (int ii = 0; ii < 4; ++ii) {
            int t = t0 + ty * 4 + ii;
#pragma unroll
            for (int jj = 0; jj < 4; jj += 2) {
                int o = tx * 4 + jj;
                size_t w = ((size_t)bh * T_ + t) * 32 + (o >> 1);
                gq[w] = h2(acc[ii][jj] * scale, acc[ii][jj + 1] * scale);
            }
        }
    } else {
        uint32_t* gv = (uint32_t*)g_Vt;
#pragma unroll
        for (int jj = 0; jj < 4; ++jj) {
            int s = tx * 4 + jj;
#pragma unroll
            for (int ii = 0; ii < 4; ii += 2) {
                int t = t0 + ty * 4 + ii;
                size_t w = ((size_t)bh * 64 + s) * (T_ / 2) + (t >> 1);
                gv[w] = h2(acc[ii][jj], acc[ii + 1][jj]);
            }
        }
    }
}

// ---------------------------------------------------------------------------
// Kernel 2: Wp -> fp16
// ---------------------------------------------------------------------------
__global__ __launch_bounds__(256) void wp_convert_kernel(const float* __restrict__ Wp) {
    int i = blockIdx.x * 256 + threadIdx.x;
    int stride = gridDim.x * 256;
    for (; i < E_ * E_; i += stride) g_Wp[i] = __float2half(Wp[i]);
}

// ---------------------------------------------------------------------------
// Kernel 3: fp16 HMMA flash attention (max-free softmax).
// CTA = 128 threads = 4 warps; warp owns 32 q-rows (2 mtiles). KV tile = 64
// keys, double-buffered cp.async. ldmatrix.x4 fragment loads. S C-frags ->
// exp -> P A-frags in registers, per 32-key half. 3 CTAs/SM.
// Dyn smem: 2 x (9216 + 9216) = 36864 B.
// ---------------------------------------------------------------------------
constexpr int AT_K = 0;          // 64 rows x 144 B (64 fp16 + 8 pad)
constexpr int AT_V = 9216;       // 64 s-rows x 144 B (64 key-cols + pad)
constexpr int AT_BUF = 18432;
constexpr int ATTN_SMEM = 2 * AT_BUF;   // 36864

__device__ __forceinline__ void attn_load_tile(uint32_t sb, int buf, int bh, int kt,
                                               int tid) {
    uint32_t bb = sb + (buf ? AT_BUF : 0);
    const char* kp = (const char*)g_K;
    const char* vp = (const char*)g_Vt;
#pragma unroll
    for (int i = tid; i < 512; i += 128) {   // K: 64 rows x 8 chunks of 16B
        int row = i >> 3, c = i & 7;
        long gb = ((long)(bh * T_ + kt + row)) * 128 + c * 16;
        CP_ASYNC16(bb + AT_K + (uint32_t)(row * 144 + c * 16), kp + gb);
    }
#pragma unroll
    for (int i = tid; i < 512; i += 128) {   // Vt: 64 s-rows x 8 chunks
        int row = i >> 3, c = i & 7;
        long gb = ((long)(bh * 64 + row)) * (T_ * 2) + (long)kt * 2 + c * 16;
        CP_ASYNC16(bb + AT_V + (uint32_t)(row * 144 + c * 16), vp + gb);
    }
}

__global__ __launch_bounds__(128, 3) void attn_kernel() {
    extern __shared__ char smc[];
    const uint32_t sb = smem_u32(smc);

    const int tid = threadIdx.x;
    const int w = tid >> 5;
    const int lane = tid & 31;
    const int g = lane >> 2;   // row within 8
    const int tg = lane & 3;   // col-pair index
    // ldmatrix lane-address selectors (B-style x4: {rows 0-7,+0},{0-7,+16},{8-15,+0},{8-15,+16})
    const int rowsel = (lane & 7) + ((lane & 16) >> 1);
    const int koff = (lane & 8) * 2;

    const int q0 = blockIdx.x * 128;
    const int bh = blockIdx.z * H_ + blockIdx.y;

    // ---- Q fragments from gmem (held for the whole kernel): 2 mtiles ----
    uint32_t qf[2][4][4];
    {
        const uint32_t* gq = (const uint32_t*)g_Q;
#pragma unroll
        for (int mt = 0; mt < 2; ++mt) {
            int r0 = q0 + w * 32 + mt * 16 + g;
            int base0 = (bh * T_ + r0) * 32;
            int base1 = base0 + 8 * 32;
#pragma unroll
            for (int kk = 0; kk < 4; ++kk) {
                int wd = kk * 8 + tg;
                qf[mt][kk][0] = gq[base0 + wd];
                qf[mt][kk][1] = gq[base1 + wd];
                qf[mt][kk][2] = gq[base0 + wd + 4];
                qf[mt][kk][3] = gq[base1 + wd + 4];
            }
        }
    }

    float oacc[2][8][4] = {};
    float lsum[2][2] = {};

    attn_load_tile(sb, 0, bh, 0, tid);
    CP_COMMIT();

    for (int it = 0; it < 32; ++it) {
        const int buf = it & 1;
        if (it < 31) {
            attn_load_tile(sb, buf ^ 1, bh, (it + 1) * 64, tid);
            CP_COMMIT();
            CP_WAIT1();
        } else {
            CP_WAIT0();
        }
        __syncthreads();

        const uint32_t bb = sb + (buf ? AT_BUF : 0);

#pragma unroll
        for (int kh = 0; kh < 2; ++kh) {  // 32-key halves
            // ---- S = Q K^T for keys [kh*32, kh*32+32) ----
            float sacc[2][4][4] = {};
#pragma unroll
            for (int kk = 0; kk < 4; ++kk) {
                uint32_t kf[8];
#pragma unroll
                for (int p = 0; p < 2; ++p) {
                    uint32_t a = bb + AT_K +
                        (uint32_t)((kh * 32 + p * 16 + rowsel) * 144 + kk * 32 + koff);
                    LDSM4(kf[p * 4], kf[p * 4 + 1], kf[p * 4 + 2], kf[p * 4 + 3], a);
                }
#pragma unroll
                for (int mt = 0; mt < 2; ++mt)
#pragma unroll
                    for (int p = 0; p < 2; ++p) {
                        mma16816(sacc[mt][p * 2], qf[mt][kk], kf[p * 4], kf[p * 4 + 1]);
                        mma16816(sacc[mt][p * 2 + 1], qf[mt][kk], kf[p * 4 + 2], kf[p * 4 + 3]);
                    }
            }

            // ---- exp + P A-frags (max-free softmax) ----
            uint32_t pf[2][2][4];
#pragma unroll
            for (int mt = 0; mt < 2; ++mt)
#pragma unroll
                for (int j = 0; j < 2; ++j) {
                    float e0 = __expf(sacc[mt][2 * j][0]);
                    float e1 = __expf(sacc[mt][2 * j][1]);
                    float e2 = __expf(sacc[mt][2 * j][2]);
                    float e3 = __expf(sacc[mt][2 * j][3]);
                    float e4 = __expf(sacc[mt][2 * j + 1][0]);
                    float e5 = __expf(sacc[mt][2 * j + 1][1]);
                    float e6 = __expf(sacc[mt][2 * j + 1][2]);
                    float e7 = __expf(sacc[mt][2 * j + 1][3]);
                    lsum[mt][0] += (e0 + e1) + (e4 + e5);
                    lsum[mt][1] += (e2 + e3) + (e6 + e7);
                    pf[mt][j][0] = h2(e0, e1);
                    pf[mt][j][1] = h2(e2, e3);
                    pf[mt][j][2] = h2(e4, e5);
                    pf[mt][j][3] = h2(e6, e7);
                }

            // ---- O += P V^T for these 32 keys (2 k-tiles of 16) ----
#pragma unroll
            for (int j = 0; j < 2; ++j) {
                uint32_t vf[16];
#pragma unroll
                for (int p = 0; p < 4; ++p) {
                    uint32_t a = bb + AT_V +
                        (uint32_t)((p * 16 + rowsel) * 144 + (kh * 2 + j) * 32 + koff);
                    LDSM4(vf[p * 4], vf[p * 4 + 1], vf[p * 4 + 2], vf[p * 4 + 3], a);
                }
#pragma unroll
                for (int mt = 0; mt < 2; ++mt)
#pragma unroll
                    for (int nt = 0; nt < 8; ++nt)
                        mma16816(oacc[mt][nt], pf[mt][j], vf[nt * 2], vf[nt * 2 + 1]);
            }
        }
        __syncthreads();
    }

    // ---- epilogue: reduce row sums over quad, normalize, write fp16 C ----
    uint32_t* gc = (uint32_t*)g_C;
#pragma unroll
    for (int mt = 0; mt < 2; ++mt) {
        float l0 = lsum[mt][0], l1 = lsum[mt][1];
        l0 += __shfl_xor_sync(0xffffffffu, l0, 1);
        l0 += __shfl_xor_sync(0xffffffffu, l0, 2);
        l1 += __shfl_xor_sync(0xffffffffu, l1, 1);
        l1 += __shfl_xor_sync(0xffffffffu, l1, 2);
        const float inv0 = 1.0f / l0;
        const float inv1 = 1.0f / l1;

        int r0 = q0 + w * 32 + mt * 16 + g;
        long wb0 = ((long)blockIdx.z * T_ + r0) * 512 + blockIdx.y * 32;
        long wb1 = wb0 + 8 * 512;
#pragma unroll
        for (int nt = 0; nt < 8; ++nt) {
            gc[wb0 + nt * 4 + tg] = h2(oacc[mt][nt][0] * inv0, oacc[mt][nt][1] * inv0);
            gc[wb1 + nt * 4 + tg] = h2(oacc[mt][nt][2] * inv1, oacc[mt][nt][3] * inv1);
        }
    }
}

// ---------------------------------------------------------------------------
// Kernel 4: fp16 HMMA output projection. Y = C @ Wp^T + bp.
// CTA tile 128x128, k-chunk 64, 8 warps (2M x 4N -> warp tile 64x32),
// ldmatrix.x4, double-buffered cp.async. 2 CTAs/SM.
// Dyn smem: 2 x 36864 = 73728 B.
// ---------------------------------------------------------------------------
constexpr int PJ_A = 0;           // 128 rows x 144 B (64 fp16 + pad)
constexpr int PJ_B = 18432;
constexpr int PJ_BUF = 36864;
constexpr int PROJ_SMEM = 2 * PJ_BUF;  // 73728

__device__ __forceinline__ void proj_load_tile(uint32_t sb, int buf, int m0, int n0,
                                               int kc, int tid) {
    uint32_t bb = sb + (buf ? PJ_BUF : 0);
    const char* ap = (const char*)g_C;
    const char* bp = (const char*)g_Wp;
#pragma unroll
    for (int i = tid; i < 1024; i += 256) {  // 128 rows x 8 chunks of 16B
        int row = i >> 3, c = i & 7;
        uint32_t so = (uint32_t)(row * 144 + c * 16);
        long ga = ((long)(m0 + row) * E_ + kc * 64) * 2 + c * 16;
        long gb = ((long)(n0 + row) * E_ + kc * 64) * 2 + c * 16;
        CP_ASYNC16(bb + PJ_A + so, ap + ga);
        CP_ASYNC16(bb + PJ_B + so, bp + gb);
    }
}

__global__ __launch_bounds__(256, 2) void proj_kernel(const float* __restrict__ bp,
                                                      float* __restrict__ out) {
    extern __shared__ char smc[];
    const uint32_t sb = smem_u32(smc);

    const int tid = threadIdx.x;
    const int w = tid >> 5;
    const int lane = tid & 31;
    const int g = lane >> 2;
    const int tg = lane & 3;
    const int wm = w >> 2;   // 0..1: 64-row M group
    const int wn = w & 3;    // 0..3: 32-col N group
    // ldmatrix selectors
    const int rowsel = (lane & 7) + ((lane & 16) >> 1);  // B-style
    const int koff = (lane & 8) * 2;
    const int arow = lane & 15;                           // A-style
    const int aoff = (lane >> 4) * 16;

    const int m0 = blockIdx.x * 128;
    const int n0 = blockIdx.y * 128;

    float acc[4][4][4] = {};  // [mt][nt][4]

    proj_load_tile(sb, 0, m0, n0, 0, tid);
    CP_COMMIT();

    for (int kc = 0; kc < 16; ++kc) {
        const int buf = kc & 1;
        if (kc < 15) {
            proj_load_tile(sb, buf ^ 1, m0, n0, kc + 1, tid);
            CP_COMMIT();
            CP_WAIT1();
        } else {
            CP_WAIT0();
        }
        __syncthreads();

        const uint32_t bb = sb + (buf ? PJ_BUF : 0);

#pragma unroll
        for (int kk = 0; kk < 4; ++kk) {
            uint32_t af[4][4];
#pragma unroll
            for (int mt = 0; mt < 4; ++mt) {
                uint32_t a = bb + PJ_A +
                    (uint32_t)((wm * 64 + mt * 16 + arow) * 144 + kk * 32 + aoff);
                LDSM4(af[mt][0], af[mt][1], af[mt][2], af[mt][3], a);
            }
            uint32_t bf[8];
#pragma unroll
            for (int p = 0; p < 2; ++p) {
                uint32_t a = bb + PJ_B +
                    (uint32_t)((wn * 32 + p * 16 + rowsel) * 144 + kk * 32 + koff);
                LDSM4(bf[p * 4], bf[p * 4 + 1], bf[p * 4 + 2], bf[p * 4 + 3], a);
            }
#pragma unroll
            for (int mt = 0; mt < 4; ++mt)
#pragma unroll
                for (int nt = 0; nt < 4; ++nt)
                    mma16816(acc[mt][nt], af[mt], bf[nt * 2], bf[nt * 2 + 1]);
        }
        __syncthreads();
    }

    // epilogue: add bias, write fp32
#pragma unroll
    for (int mt = 0; mt < 4; ++mt) {
        int mr0 = m0 + wm * 64 + mt * 16 + g;
        int mr1 = mr0 + 8;
#pragma unroll
        for (int nt = 0; nt < 4; ++nt) {
            int col = n0 + wn * 32 + nt * 8 + tg * 2;
            float b0 = __ldg(bp + col);
            float b1 = __ldg(bp + col + 1);
            *(float2*)(out + (long)mr0 * E_ + col) =
                make_float2(acc[mt][nt][0] + b0, acc[mt][nt][1] + b1);
            *(float2*)(out + (long)mr1 * E_ + col) =
                make_float2(acc[mt][nt][2] + b0, acc[mt][nt][3] + b1);
        }
    }
}

// ---------------------------------------------------------------------------
// kernel_launch: inputs x, Wk, Wq, Wv, Wp, bp
// ---------------------------------------------------------------------------
extern "C" void kernel_launch(void* const* d_in, const int* in_sizes, int n_in,
                              void* d_out, int out_size) {
    (void)in_sizes; (void)n_in; (void)out_size;
    const float* x = (const float*)d_in[0];
    const float* Wk = (const float*)d_in[1];
    const float* Wq = (const float*)d_in[2];
    const float* Wv = (const float*)d_in[3];
    const float* Wp = (const float*)d_in[4];
    const float* bp = (const float*)d_in[5];
    float* out = (float*)d_out;

    constexpr int SMEM_QKV = 128 * 65 * 4;  // 33280

    cudaFuncSetAttribute(qkv_kernel, cudaFuncAttributeMaxDynamicSharedMemorySize, SMEM_QKV);
    cudaFuncSetAttribute(attn_kernel, cudaFuncAttributeMaxDynamicSharedMemorySize, ATTN_SMEM);
    cudaFuncSetAttribute(proj_kernel, cudaFuncAttributeMaxDynamicSharedMemorySize, PROJ_SMEM);

    qkv_kernel<<<dim3(T_ / 64, H_, 3 * B_), 256, SMEM_QKV>>>(x, Wq, Wk, Wv);
    wp_convert_kernel<<<256, 256>>>(Wp);
    attn_kernel<<<dim3(T_ / 128, H_, B_), 128, ATTN_SMEM>>>();
    proj_kernel<<<dim3((B_ * T_) / 128, E_ / 128), 256, PROJ_SMEM>>>(bp, out);
}

// round 11
// speedup vs baseline: 2.9580x; 1.3819x over previous
#include <cuda_runtime.h>
#include <cuda_fp16.h>
#include <cstdint>

// Problem constants
constexpr int B_ = 4;
constexpr int T_ = 2048;
constexpr int E_ = 1024;
constexpr int H_ = 16;
constexpr int S_ = 64;

// ---------------------------------------------------------------------------
// Global scratch (fp16). Static device arrays only.
// ---------------------------------------------------------------------------
__device__ __half g_Q[(size_t)B_ * H_ * T_ * S_];    // (b,h,t,s), scaled by log2e/e^.25
__device__ __half g_K[(size_t)B_ * H_ * T_ * S_];    // (b,h,t,s), scaled by 1/e^.25
__device__ __half g_V[(size_t)B_ * H_ * T_ * S_];    // (b,h,t,s)
__device__ __half g_C[(size_t)B_ * T_ * E_];         // context (b,t,e)
__device__ __half g_Wp[(size_t)E_ * E_];
__device__ __half g_W3[192 * 64];                     // fused scaled Wq|Wk|Wv (row o, col i)

// ---------------------------------------------------------------------------
// Baseline-PTX helpers (portable to plain sm_103 target)
// ---------------------------------------------------------------------------
__device__ __forceinline__ uint32_t smem_u32(const void* p) {
    uint32_t a;
    asm("{ .reg .u64 t; cvta.to.shared.u64 t, %1; cvt.u32.u64 %0, t; }"
        : "=r"(a) : "l"(p));
    return a;
}

#define LDSM4(r0, r1, r2, r3, addr) \
    asm volatile("ldmatrix.sync.aligned.m8n8.x4.shared.b16 {%0,%1,%2,%3}, [%4];" \
                 : "=r"(r0), "=r"(r1), "=r"(r2), "=r"(r3) : "r"(addr))
#define LDSM4T(r0, r1, r2, r3, addr) \
    asm volatile("ldmatrix.sync.aligned.m8n8.x4.trans.shared.b16 {%0,%1,%2,%3}, [%4];" \
                 : "=r"(r0), "=r"(r1), "=r"(r2), "=r"(r3) : "r"(addr))

#define CP_ASYNC16(dst, src) \
    asm volatile("cp.async.cg.shared.global [%0], [%1], 16;" :: "r"(dst), "l"(src) : "memory")
#define CP_COMMIT() asm volatile("cp.async.commit_group;" ::: "memory")
#define CP_WAIT1()  asm volatile("cp.async.wait_group 1;" ::: "memory")
#define CP_WAIT0()  asm volatile("cp.async.wait_group 0;" ::: "memory")

// m16n8k16 row.col fp16 -> fp32 accumulate (HMMA)
__device__ __forceinline__ void mma16816(float d[4], const uint32_t a[4],
                                         uint32_t b0, uint32_t b1) {
    asm volatile(
        "mma.sync.aligned.m16n8k16.row.col.f32.f16.f16.f32 "
        "{%0,%1,%2,%3}, {%4,%5,%6,%7}, {%8,%9}, {%0,%1,%2,%3};"
        : "+f"(d[0]), "+f"(d[1]), "+f"(d[2]), "+f"(d[3])
        : "r"(a[0]), "r"(a[1]), "r"(a[2]), "r"(a[3]), "r"(b0), "r"(b1));
}

__device__ __forceinline__ uint32_t h2(float a, float b) {
    __half2 v = __float22half2_rn(make_float2(a, b));
    return *reinterpret_cast<uint32_t*>(&v);
}

__device__ __forceinline__ float ex2(float x) {
    float r;
    asm("ex2.approx.f32 %0, %1;" : "=f"(r) : "f"(x));
    return r;
}

// ---------------------------------------------------------------------------
// Kernel 1: weight conversion. Wp -> fp16; Wq/Wk/Wv -> fused scaled fp16 panel.
// ---------------------------------------------------------------------------
__global__ __launch_bounds__(256) void convert_kernel(const float* __restrict__ Wq,
                                                      const float* __restrict__ Wk,
                                                      const float* __restrict__ Wv,
                                                      const float* __restrict__ Wp) {
    int i = blockIdx.x * 256 + threadIdx.x;
    const int stride = gridDim.x * 256;
    for (int j = i; j < E_ * E_; j += stride) g_Wp[j] = __float2half(Wp[j]);

    if (i < 3 * 64 * 64) {
        int kind = i >> 12;
        int idx = i & 4095;
        const float* W = (kind == 0) ? Wq : (kind == 1) ? Wk : Wv;
        // Q scale folds log2e (softmax via 2^x); Q,K each get e^-0.25.
        float scale = (kind == 0) ? 0.17677669529663688f * 1.4426950408889634f
                    : (kind == 1) ? 0.17677669529663688f : 1.0f;
        g_W3[i] = __float2half(W[idx] * scale);
    }
}

// ---------------------------------------------------------------------------
// Kernel 2: HMMA QKV projection. CTA = (t-tile of 128, head, batch).
// X tile split exactly into fp16 hi+lo in smem; Q|K|V = (Xh+Xl) @ W3^T via
// m16n8k16, M=128 N=192 K=64. 256 threads, 8 warps x 16 rows. 1 CTA/SM.
// Dyn smem: 2*18432 + 27648 = 64512 B.
// ---------------------------------------------------------------------------
constexpr int QK_XH = 0;          // 128 x 144B
constexpr int QK_XL = 18432;
constexpr int QK_W = 36864;       // 192 x 144B
constexpr int QKV_SMEM = 64512;

__global__ __launch_bounds__(256) void qkv_kernel(const float* __restrict__ x) {
    extern __shared__ char smc[];
    const uint32_t sb = smem_u32(smc);

    const int tid = threadIdx.x;
    const int w = tid >> 5;
    const int lane = tid & 31;
    const int g = lane >> 2, tg = lane & 3;
    const int arow = lane & 15, aoff = (lane >> 4) * 16;              // A-style ldsm
    const int rowsel = (lane & 7) + ((lane & 16) >> 1);               // B-style ldsm
    const int koff = (lane & 8) * 2;

    const int t0 = blockIdx.x * 128;
    const int h = blockIdx.y;
    const int b = blockIdx.z;
    const int bh = b * H_ + h;

    // W panel via cp.async (192 rows x 128B)
    {
        const char* wp = (const char*)g_W3;
        for (int i = tid; i < 1536; i += 256) {
            int row = i >> 3, c = i & 7;
            CP_ASYNC16(sb + QK_W + (uint32_t)(row * 144 + c * 16), wp + row * 128 + c * 16);
        }
        CP_COMMIT();
    }

    // X tile fp32 -> exact fp16 hi/lo split in smem
    {
        const float4* xp = (const float4*)(x + ((size_t)b * T_ + t0) * E_ + h * S_);
        for (int i = tid; i < 128 * 16; i += 256) {
            int r = i >> 4, c4 = i & 15;
            float4 v = xp[(size_t)r * 256 + c4];
            uint32_t hw0 = h2(v.x, v.y), hw1 = h2(v.z, v.w);
            __half2 hh0 = *(__half2*)&hw0, hh1 = *(__half2*)&hw1;
            float2 f0 = __half22float2(hh0), f1 = __half22float2(hh1);
            uint32_t lw0 = h2(v.x - f0.x, v.y - f0.y);
            uint32_t lw1 = h2(v.z - f1.x, v.w - f1.y);
            *(uint2*)(smc + QK_XH + r * 144 + c4 * 8) = make_uint2(hw0, hw1);
            *(uint2*)(smc + QK_XL + r * 144 + c4 * 8) = make_uint2(lw0, lw1);
        }
    }
    CP_WAIT0();
    __syncthreads();

    // A fragments (hi and lo) for this warp's 16 rows
    uint32_t ah[4][4], al[4][4];
#pragma unroll
    for (int kk = 0; kk < 4; ++kk) {
        uint32_t a = sb + QK_XH + (uint32_t)((w * 16 + arow) * 144 + kk * 32 + aoff);
        LDSM4(ah[kk][0], ah[kk][1], ah[kk][2], ah[kk][3], a);
        uint32_t a2 = sb + QK_XL + (uint32_t)((w * 16 + arow) * 144 + kk * 32 + aoff);
        LDSM4(al[kk][0], al[kk][1], al[kk][2], al[kk][3], a2);
    }

    float acc[24][4] = {};
#pragma unroll
    for (int kk = 0; kk < 4; ++kk) {
#pragma unroll
        for (int ntp = 0; ntp < 12; ++ntp) {
            uint32_t b0, b1, b2, b3;
            uint32_t a = sb + QK_W + (uint32_t)((ntp * 16 + rowsel) * 144 + kk * 32 + koff);
            LDSM4(b0, b1, b2, b3, a);
            mma16816(acc[2 * ntp], ah[kk], b0, b1);
            mma16816(acc[2 * ntp + 1], ah[kk], b2, b3);
            mma16816(acc[2 * ntp], al[kk], b0, b1);
            mma16816(acc[2 * ntp + 1], al[kk], b2, b3);
        }
    }

    // Store Q | K | V (all (b,h,t,s) fp16)
    uint32_t* dsts[3] = {(uint32_t*)g_Q, (uint32_t*)g_K, (uint32_t*)g_V};
    const int r0 = t0 + w * 16 + g;
    const size_t wb0 = ((size_t)bh * T_ + r0) * 32;
    const size_t wb1 = wb0 + 8 * 32;
#pragma unroll
    for (int nt = 0; nt < 24; ++nt) {
        uint32_t* dst = dsts[nt >> 3];
        int wo = (nt & 7) * 4 + tg;
        dst[wb0 + wo] = h2(acc[nt][0], acc[nt][1]);
        dst[wb1 + wo] = h2(acc[nt][2], acc[nt][3]);
    }
}

// ---------------------------------------------------------------------------
// Kernel 3: fp16 HMMA flash attention (max-free softmax via 2^S).
// CTA = 128 threads = 4 warps; warp owns 32 q-rows. KV tile = 64 keys,
// double-buffered cp.async. K via ldmatrix, V via ldmatrix.trans (no
// pre-transpose needed). 3 CTAs/SM. Dyn smem: 2 x 18432 = 36864 B.
// ---------------------------------------------------------------------------
constexpr int AT_K = 0;          // 64 rows x 144 B
constexpr int AT_V = 9216;       // 64 rows x 144 B
constexpr int AT_BUF = 18432;
constexpr int ATTN_SMEM = 2 * AT_BUF;

__device__ __forceinline__ void attn_load_tile(uint32_t sb, int buf, int bh, int kt,
                                               int tid) {
    uint32_t bb = sb + (buf ? AT_BUF : 0);
    const char* kp = (const char*)g_K;
    const char* vp = (const char*)g_V;
#pragma unroll
    for (int i = tid; i < 512; i += 128) {   // 64 rows x 8 chunks of 16B
        int row = i >> 3, c = i & 7;
        long gb = ((long)(bh * T_ + kt + row)) * 128 + c * 16;
        CP_ASYNC16(bb + AT_K + (uint32_t)(row * 144 + c * 16), kp + gb);
        CP_ASYNC16(bb + AT_V + (uint32_t)(row * 144 + c * 16), vp + gb);
    }
}

__global__ __launch_bounds__(128, 3) void attn_kernel() {
    extern __shared__ char smc[];
    const uint32_t sb = smem_u32(smc);

    const int tid = threadIdx.x;
    const int w = tid >> 5;
    const int lane = tid & 31;
    const int g = lane >> 2;
    const int tg = lane & 3;
    const int rowsel = (lane & 7) + ((lane & 16) >> 1);   // B-style (K)
    const int koff = (lane & 8) * 2;
    const int arow = lane & 15;                            // trans-style (V)
    const int aoff = (lane >> 4) * 16;

    const int q0 = blockIdx.x * 128;
    const int bh = blockIdx.z * H_ + blockIdx.y;

    // ---- Q fragments from gmem (held for the whole kernel): 2 mtiles ----
    uint32_t qf[2][4][4];
    {
        const uint32_t* gq = (const uint32_t*)g_Q;
#pragma unroll
        for (int mt = 0; mt < 2; ++mt) {
            int r0 = q0 + w * 32 + mt * 16 + g;
            int base0 = (bh * T_ + r0) * 32;
            int base1 = base0 + 8 * 32;
#pragma unroll
            for (int kk = 0; kk < 4; ++kk) {
                int wd = kk * 8 + tg;
                qf[mt][kk][0] = gq[base0 + wd];
                qf[mt][kk][1] = gq[base1 + wd];
                qf[mt][kk][2] = gq[base0 + wd + 4];
                qf[mt][kk][3] = gq[base1 + wd + 4];
            }
        }
    }

    float oacc[2][8][4] = {};
    float lsum[2][2] = {};

    attn_load_tile(sb, 0, bh, 0, tid);
    CP_COMMIT();

    for (int it = 0; it < 32; ++it) {
        const int buf = it & 1;
        if (it < 31) {
            attn_load_tile(sb, buf ^ 1, bh, (it + 1) * 64, tid);
            CP_COMMIT();
            CP_WAIT1();
        } else {
            CP_WAIT0();
        }
        __syncthreads();

        const uint32_t bb = sb + (buf ? AT_BUF : 0);

#pragma unroll
        for (int kh = 0; kh < 2; ++kh) {  // 32-key halves
            // ---- S = Q K^T for keys [kh*32, kh*32+32) ----
            float sacc[2][4][4] = {};
#pragma unroll
            for (int kk = 0; kk < 4; ++kk) {
                uint32_t kf[8];
#pragma unroll
                for (int p = 0; p < 2; ++p) {
                    uint32_t a = bb + AT_K +
                        (uint32_t)((kh * 32 + p * 16 + rowsel) * 144 + kk * 32 + koff);
                    LDSM4(kf[p * 4], kf[p * 4 + 1], kf[p * 4 + 2], kf[p * 4 + 3], a);
                }
#pragma unroll
                for (int mt = 0; mt < 2; ++mt)
#pragma unroll
                    for (int p = 0; p < 2; ++p) {
                        mma16816(sacc[mt][p * 2], qf[mt][kk], kf[p * 4], kf[p * 4 + 1]);
                        mma16816(sacc[mt][p * 2 + 1], qf[mt][kk], kf[p * 4 + 2], kf[p * 4 + 3]);
                    }
            }

            // ---- P = 2^S (max-free softmax; log2e folded into Q scale) ----
            uint32_t pf[2][2][4];
#pragma unroll
            for (int mt = 0; mt < 2; ++mt)
#pragma unroll
                for (int j = 0; j < 2; ++j) {
                    float e0 = ex2(sacc[mt][2 * j][0]);
                    float e1 = ex2(sacc[mt][2 * j][1]);
                    float e2 = ex2(sacc[mt][2 * j][2]);
                    float e3 = ex2(sacc[mt][2 * j][3]);
                    float e4 = ex2(sacc[mt][2 * j + 1][0]);
                    float e5 = ex2(sacc[mt][2 * j + 1][1]);
                    float e6 = ex2(sacc[mt][2 * j + 1][2]);
                    float e7 = ex2(sacc[mt][2 * j + 1][3]);
                    lsum[mt][0] += (e0 + e1) + (e4 + e5);
                    lsum[mt][1] += (e2 + e3) + (e6 + e7);
                    pf[mt][j][0] = h2(e0, e1);
                    pf[mt][j][1] = h2(e2, e3);
                    pf[mt][j][2] = h2(e4, e5);
                    pf[mt][j][3] = h2(e6, e7);
                }

            // ---- O += P V (B-frags via ldmatrix.trans of (key,s) tile) ----
#pragma unroll
            for (int j = 0; j < 2; ++j) {
                uint32_t vf[16];
#pragma unroll
                for (int p = 0; p < 4; ++p) {
                    uint32_t a = bb + AT_V +
                        (uint32_t)((kh * 32 + j * 16 + arow) * 144 + p * 32 + aoff);
                    LDSM4T(vf[p * 4], vf[p * 4 + 1], vf[p * 4 + 2], vf[p * 4 + 3], a);
                }
#pragma unroll
                for (int mt = 0; mt < 2; ++mt)
#pragma unroll
                    for (int nt = 0; nt < 8; ++nt)
                        mma16816(oacc[mt][nt], pf[mt][j], vf[nt * 2], vf[nt * 2 + 1]);
            }
        }
        __syncthreads();
    }

    // ---- epilogue: reduce row sums over quad, normalize, write fp16 C ----
    uint32_t* gc = (uint32_t*)g_C;
#pragma unroll
    for (int mt = 0; mt < 2; ++mt) {
        float l0 = lsum[mt][0], l1 = lsum[mt][1];
        l0 += __shfl_xor_sync(0xffffffffu, l0, 1);
        l0 += __shfl_xor_sync(0xffffffffu, l0, 2);
        l1 += __shfl_xor_sync(0xffffffffu, l1, 1);
        l1 += __shfl_xor_sync(0xffffffffu, l1, 2);
        const float inv0 = 1.0f / l0;
        const float inv1 = 1.0f / l1;

        int r0 = q0 + w * 32 + mt * 16 + g;
        long wb0 = ((long)blockIdx.z * T_ + r0) * 512 + blockIdx.y * 32;
        long wb1 = wb0 + 8 * 512;
#pragma unroll
        for (int nt = 0; nt < 8; ++nt) {
            gc[wb0 + nt * 4 + tg] = h2(oacc[mt][nt][0] * inv0, oacc[mt][nt][1] * inv0);
            gc[wb1 + nt * 4 + tg] = h2(oacc[mt][nt][2] * inv1, oacc[mt][nt][3] * inv1);
        }
    }
}

// ---------------------------------------------------------------------------
// Kernel 4: fp16 HMMA output projection. Y = C @ Wp^T + bp.
// CTA tile 128x128, k-chunk 64, 8 warps (warp tile 64x32), ldmatrix.x4,
// double-buffered cp.async. 2 CTAs/SM. Dyn smem: 2 x 36864 = 73728 B.
// ---------------------------------------------------------------------------
constexpr int PJ_A = 0;           // 128 rows x 144 B
constexpr int PJ_B = 18432;
constexpr int PJ_BUF = 36864;
constexpr int PROJ_SMEM = 2 * PJ_BUF;

__device__ __forceinline__ void proj_load_tile(uint32_t sb, int buf, int m0, int n0,
                                               int kc, int tid) {
    uint32_t bb = sb + (buf ? PJ_BUF : 0);
    const char* ap = (const char*)g_C;
    const char* bp = (const char*)g_Wp;
#pragma unroll
    for (int i = tid; i < 1024; i += 256) {  // 128 rows x 8 chunks of 16B
        int row = i >> 3, c = i & 7;
        uint32_t so = (uint32_t)(row * 144 + c * 16);
        long ga = ((long)(m0 + row) * E_ + kc * 64) * 2 + c * 16;
        long gb = ((long)(n0 + row) * E_ + kc * 64) * 2 + c * 16;
        CP_ASYNC16(bb + PJ_A + so, ap + ga);
        CP_ASYNC16(bb + PJ_B + so, bp + gb);
    }
}

__global__ __launch_bounds__(256, 2) void proj_kernel(const float* __restrict__ bp,
                                                      float* __restrict__ out) {
    extern __shared__ char smc[];
    const uint32_t sb = smem_u32(smc);

    const int tid = threadIdx.x;
    const int w = tid >> 5;
    const int lane = tid & 31;
    const int g = lane >> 2;
    const int tg = lane & 3;
    const int wm = w >> 2;
    const int wn = w & 3;
    const int rowsel = (lane & 7) + ((lane & 16) >> 1);
    const int koff = (lane & 8) * 2;
    const int arow = lane & 15;
    const int aoff = (lane >> 4) * 16;

    const int m0 = blockIdx.x * 128;
    const int n0 = blockIdx.y * 128;

    float acc[4][4][4] = {};

    proj_load_tile(sb, 0, m0, n0, 0, tid);
    CP_COMMIT();

    for (int kc = 0; kc < 16; ++kc) {
        const int buf = kc & 1;
        if (kc < 15) {
            proj_load_tile(sb, buf ^ 1, m0, n0, kc + 1, tid);
            CP_COMMIT();
            CP_WAIT1();
        } else {
            CP_WAIT0();
        }
        __syncthreads();

        const uint32_t bb = sb + (buf ? PJ_BUF : 0);

#pragma unroll
        for (int kk = 0; kk < 4; ++kk) {
            uint32_t af[4][4];
#pragma unroll
            for (int mt = 0; mt < 4; ++mt) {
                uint32_t a = bb + PJ_A +
                    (uint32_t)((wm * 64 + mt * 16 + arow) * 144 + kk * 32 + aoff);
                LDSM4(af[mt][0], af[mt][1], af[mt][2], af[mt][3], a);
            }
            uint32_t bf[8];
#pragma unroll
            for (int p = 0; p < 2; ++p) {
                uint32_t a = bb + PJ_B +
                    (uint32_t)((wn * 32 + p * 16 + rowsel) * 144 + kk * 32 + koff);
                LDSM4(bf[p * 4], bf[p * 4 + 1], bf[p * 4 + 2], bf[p * 4 + 3], a);
            }
#pragma unroll
            for (int mt = 0; mt < 4; ++mt)
#pragma unroll
                for (int nt = 0; nt < 4; ++nt)
                    mma16816(acc[mt][nt], af[mt], bf[nt * 2], bf[nt * 2 + 1]);
        }
        __syncthreads();
    }

    // epilogue: add bias, write fp32
#pragma unroll
    for (int mt = 0; mt < 4; ++mt) {
        int mr0 = m0 + wm * 64 + mt * 16 + g;
        int mr1 = mr0 + 8;
#pragma unroll
        for (int nt = 0; nt < 4; ++nt) {
            int col = n0 + wn * 32 + nt * 8 + tg * 2;
            float b0 = __ldg(bp + col);
            float b1 = __ldg(bp + col + 1);
            *(float2*)(out + (long)mr0 * E_ + col) =
                make_float2(acc[mt][nt][0] + b0, acc[mt][nt][1] + b1);
            *(float2*)(out + (long)mr1 * E_ + col) =
                make_float2(acc[mt][nt][2] + b0, acc[mt][nt][3] + b1);
        }
    }
}

// ---------------------------------------------------------------------------
// kernel_launch: inputs x, Wk, Wq, Wv, Wp, bp
// ---------------------------------------------------------------------------
extern "C" void kernel_launch(void* const* d_in, const int* in_sizes, int n_in,
                              void* d_out, int out_size) {
    (void)in_sizes; (void)n_in; (void)out_size;
    const float* x = (const float*)d_in[0];
    const float* Wk = (const float*)d_in[1];
    const float* Wq = (const float*)d_in[2];
    const float* Wv = (const float*)d_in[3];
    const float* Wp = (const float*)d_in[4];
    const float* bp = (const float*)d_in[5];
    float* out = (float*)d_out;

    cudaFuncSetAttribute(qkv_kernel, cudaFuncAttributeMaxDynamicSharedMemorySize, QKV_SMEM);
    cudaFuncSetAttribute(attn_kernel, cudaFuncAttributeMaxDynamicSharedMemorySize, ATTN_SMEM);
    cudaFuncSetAttribute(proj_kernel, cudaFuncAttributeMaxDynamicSharedMemorySize, PROJ_SMEM);

    convert_kernel<<<256, 256>>>(Wq, Wk, Wv, Wp);
    qkv_kernel<<<dim3(T_ / 128, H_, B_), 256, QKV_SMEM>>>(x);
    attn_kernel<<<dim3(T_ / 128, H_, B_), 128, ATTN_SMEM>>>();
    proj_kernel<<<dim3((B_ * T_) / 128, E_ / 128), 256, PROJ_SMEM>>>(bp, out);
}